// round 8
// baseline (speedup 1.0000x reference)
#include <cuda_runtime.h>
#include <cuda_fp16.h>
#include <cstdint>
#include <cstddef>

// Problem dims (fixed by the dataset)
#define SEQ_L 2048
#define BATCH 8
#define DIM   2048
#define M_ROWS (SEQ_L * BATCH)   // 16384
#define K_DIM  DIM
#define N_DIM  DIM
#define LANES  (BATCH * DIM)     // 16384

// Scan segmentation
#define NSEG 8
#define SEGLEN (SEQ_L / NSEG)    // 256

// GEMM tiling: CTA 128(M) x 256(N), 8 warps of 64x64, KT=64 (128B rows)
#define MT 128
#define NT 256
#define KT 64
#define NCHUNK (K_DIM / KT)      // 32
#define ROWB 144                 // 128B data + 16B pad (conflict-free ldmatrix)

#define OFF_A 0
#define OFF_B (128 * ROWB)            // 18432
#define STAGE ((128 + 256) * ROWB)    // 55296
#define SMEM_TOTAL (2 * STAGE)        // 110592

// Scratch (device globals — allocation-free rule)
__device__ __half g_ah[(size_t)M_ROWS * K_DIM];
__device__ __half g_wh[(size_t)N_DIM * K_DIM];
__device__ float  g_segend[NSEG * LANES];

// ---------------- PTX helpers (sm_80-era only: safe at compute_103) ----------------
__device__ __forceinline__ uint32_t smem_u32(const void* p) {
    uint32_t a;
    asm("{ .reg .u64 t; cvta.to.shared.u64 t, %1; cvt.u32.u64 %0, t; }"
        : "=r"(a) : "l"(p));
    return a;
}

__device__ __forceinline__ void cp_async16(uint32_t saddr, const void* gaddr) {
    asm volatile("cp.async.cg.shared.global [%0], [%1], 16;"
                 :: "r"(saddr), "l"(gaddr) : "memory");
}

__device__ __forceinline__ void ldsm_x4(uint32_t (&r)[4], uint32_t addr) {
    asm volatile("ldmatrix.sync.aligned.m8n8.x4.shared.b16 {%0,%1,%2,%3}, [%4];"
                 : "=r"(r[0]), "=r"(r[1]), "=r"(r[2]), "=r"(r[3]) : "r"(addr));
}

__device__ __forceinline__ void mma_f16(float (&d)[4], const uint32_t (&a)[4],
                                        const uint32_t* b) {
    asm volatile(
        "mma.sync.aligned.m16n8k16.row.col.f32.f16.f16.f32 "
        "{%0,%1,%2,%3}, {%4,%5,%6,%7}, {%8,%9}, {%0,%1,%2,%3};"
        : "+f"(d[0]), "+f"(d[1]), "+f"(d[2]), "+f"(d[3])
        : "r"(a[0]), "r"(a[1]), "r"(a[2]), "r"(a[3]), "r"(b[0]), "r"(b[1]));
}

// ---------------- Scan phase A: per-segment local scan, save segment-end state ----
__global__ void __launch_bounds__(256) scanA_kernel(const float* __restrict__ x,
                                                    const float* __restrict__ fparam) {
    const int lane = blockIdx.x * blockDim.x + threadIdx.x;  // 0..16383
    const int seg = blockIdx.y;
    const float f = 1.0f / (1.0f + expf(-fparam[lane & (DIM - 1)]));
    const float* px = x + (size_t)seg * SEGLEN * LANES + lane;
    float c = 0.0f;
    constexpr int U = 16;
    for (int t = 0; t < SEGLEN; t += U) {
        float xv[U];
#pragma unroll
        for (int u = 0; u < U; u++) xv[u] = px[(t + u) * LANES];
#pragma unroll
        for (int u = 0; u < U; u++) c = fmaf(f, c, xv[u]);
    }
    g_segend[seg * LANES + lane] = c;
}

// ---------------- Scan phase B: propagate carry, rescan, emit fp16 ----------
__global__ void __launch_bounds__(256) scanB_kernel(const float* __restrict__ x,
                                                    const float* __restrict__ xml,
                                                    const float* __restrict__ fparam) {
    const int lane = blockIdx.x * blockDim.x + threadIdx.x;
    const int seg = blockIdx.y;
    const float f = 1.0f / (1.0f + expf(-fparam[lane & (DIM - 1)]));
    const float omf = 1.0f - f;

    // f^SEGLEN by repeated squaring (SEGLEN = 256 = 2^8)
    float f256 = f;
#pragma unroll
    for (int i = 0; i < 8; i++) f256 *= f256;

    // G = global conv state entering this segment; fs = f^(seg*SEGLEN)
    float G = 0.0f, fs = 1.0f;
    for (int s = 0; s < seg; s++) {
        G = fmaf(f256, G, g_segend[s * LANES + lane]);
        fs *= f256;
    }

    float c = G;
    float m = xml[lane] * fs;
    const float* px = x + (size_t)seg * SEGLEN * LANES + lane;
    __half* ph = g_ah + (size_t)seg * SEGLEN * LANES + lane;

    constexpr int U = 16;
    for (int t = 0; t < SEGLEN; t += U) {
        float xv[U];
#pragma unroll
        for (int u = 0; u < U; u++) xv[u] = px[(t + u) * LANES];
#pragma unroll
        for (int u = 0; u < U; u++) {
            c = fmaf(f, c, xv[u]);
            m *= f;
            ph[(t + u) * LANES] = __float2half_rn(fmaf(omf, c, m));
        }
    }
}

// ---------------- W -> fp16 ----------
__global__ void __launch_bounds__(256) whalf_kernel(const float* __restrict__ W) {
    const int i = blockIdx.x * blockDim.x + threadIdx.x;
    g_wh[i] = __float2half_rn(W[i]);
}

// ---------------- GEMM: 1-pass fp16, fp32 accum, KT=64, frag pipeline ----------
__device__ __forceinline__ void load_chunk(uint32_t sb, int tid, int m0, int n0, int ck) {
    const uint32_t tb = sb + (uint32_t)(ck & 1) * STAGE;
    const int koff = ck * KT;
    // A: 128 rows x 128B; thread -> row=tid/2, half=(tid&1)*64B
    {
        const int row = tid >> 1;
        const int half = tid & 1;
        const size_t ga = (size_t)(m0 + row) * K_DIM + koff + half * 32;
        const uint32_t sa = tb + OFF_A + (uint32_t)row * ROWB + half * 64;
#pragma unroll
        for (int s = 0; s < 4; s++) cp_async16(sa + s * 16, g_ah + ga + s * 8);
    }
    // B: 256 rows x 128B; thread -> row=tid, 8 x 16B
    {
        const size_t gb = (size_t)(n0 + tid) * K_DIM + koff;
        const uint32_t sB = tb + OFF_B + (uint32_t)tid * ROWB;
#pragma unroll
        for (int s = 0; s < 8; s++) cp_async16(sB + s * 16, g_wh + gb + s * 8);
    }
    asm volatile("cp.async.commit_group;" ::: "memory");
}

__global__ void __launch_bounds__(256) gemm_kernel(float* __restrict__ out) {
    extern __shared__ char smem[];
    const uint32_t sb = smem_u32(smem);
    const int tid = threadIdx.x;
    const int lid = tid & 31;
    const int wid = tid >> 5;
    const int wm = wid & 1;      // 2 warps along M (64 rows each)
    const int wn = wid >> 1;     // 4 warps along N (64 cols each)
    const int n0 = blockIdx.x * NT;
    const int m0 = blockIdx.y * MT;

    float acc[4][8][4];
#pragma unroll
    for (int a = 0; a < 4; a++)
#pragma unroll
        for (int b = 0; b < 8; b++)
#pragma unroll
            for (int c = 0; c < 4; c++) acc[a][b][c] = 0.0f;

    // ldmatrix per-lane relative offsets (layouts validated in R4-R7 passes).
    uint32_t relA[4], relB[4];
#pragma unroll
    for (int mt = 0; mt < 4; mt++)
        relA[mt] = (uint32_t)((wm * 64 + mt * 16 + (lid & 15)) * ROWB + (lid >> 4) * 16);
#pragma unroll
    for (int p = 0; p < 4; p++)
        relB[p] = (uint32_t)((wn * 64 + p * 16 + ((lid >> 4) << 3) + (lid & 7)) * ROWB
                             + ((lid >> 3) & 1) * 16);

    load_chunk(sb, tid, m0, n0, 0);

    uint32_t afr[2][4][4], bfr[2][4][4];

    for (int i = 0; i < NCHUNK; i++) {
        if (i + 1 < NCHUNK) {
            load_chunk(sb, tid, m0, n0, i + 1);
            asm volatile("cp.async.wait_group 1;" ::: "memory");
        } else {
            asm volatile("cp.async.wait_group 0;" ::: "memory");
        }
        __syncthreads();

        const uint32_t base = sb + (uint32_t)(i & 1) * STAGE;

        // prime k-step 0
#pragma unroll
        for (int mt = 0; mt < 4; mt++) ldsm_x4(afr[0][mt], base + OFF_A + relA[mt]);
#pragma unroll
        for (int p = 0; p < 4; p++)   ldsm_x4(bfr[0][p], base + OFF_B + relB[p]);

#pragma unroll
        for (int ks = 0; ks < 4; ks++) {
            const int cur = ks & 1;
            if (ks < 3) {
                const uint32_t ko = (uint32_t)(ks + 1) * 32;   // 16 fp16 = 32B
                const int nxt = cur ^ 1;
#pragma unroll
                for (int mt = 0; mt < 4; mt++)
                    ldsm_x4(afr[nxt][mt], base + OFF_A + relA[mt] + ko);
#pragma unroll
                for (int p = 0; p < 4; p++)
                    ldsm_x4(bfr[nxt][p], base + OFF_B + relB[p] + ko);
            }
#pragma unroll
            for (int mt = 0; mt < 4; mt++)
#pragma unroll
                for (int nt = 0; nt < 8; nt++)
                    mma_f16(acc[mt][nt], afr[cur][mt], &bfr[cur][nt >> 1][(nt & 1) * 2]);
        }
        __syncthreads();
    }

    // Epilogue: fragment lane l -> row l/4 (+8), cols 2(l%4), +1.
    const int l4 = lid >> 2;
    const int l2 = (lid & 3) * 2;
#pragma unroll
    for (int mt = 0; mt < 4; mt++) {
        const int r0 = m0 + wm * 64 + mt * 16 + l4;
#pragma unroll
        for (int nt = 0; nt < 8; nt++) {
            const int cn = n0 + wn * 64 + nt * 8 + l2;
            *reinterpret_cast<float2*>(out + (size_t)r0 * N_DIM + cn) =
                make_float2(acc[mt][nt][0], acc[mt][nt][1]);
            *reinterpret_cast<float2*>(out + (size_t)(r0 + 8) * N_DIM + cn) =
                make_float2(acc[mt][nt][2], acc[mt][nt][3]);
        }
    }
}

// ---------------- launch ----------------
extern "C" void kernel_launch(void* const* d_in, const int* in_sizes, int n_in,
                              void* d_out, int out_size) {
    const float *x = nullptr, *xml = nullptr, *fp = nullptr, *W = nullptr;
    for (int i = 0; i < n_in; i++) {
        int s = in_sizes[i];
        if (s == SEQ_L * BATCH * DIM)      x   = (const float*)d_in[i];
        else if (s == BATCH * DIM)         xml = (const float*)d_in[i];
        else if (s == DIM)                 fp  = (const float*)d_in[i];
        else if (s == DIM * DIM)           W   = (const float*)d_in[i];
    }

    cudaFuncSetAttribute(gemm_kernel, cudaFuncAttributeMaxDynamicSharedMemorySize, SMEM_TOTAL);

    scanA_kernel<<<dim3(LANES / 256, NSEG), 256>>>(x, fp);
    scanB_kernel<<<dim3(LANES / 256, NSEG), 256>>>(x, xml, fp);
    whalf_kernel<<<(N_DIM * K_DIM) / 256, 256>>>(W);
    gemm_kernel<<<dim3(N_DIM / NT, M_ROWS / MT), 256, SMEM_TOTAL>>>((float*)d_out);
}

// round 9
// speedup vs baseline: 1.3584x; 1.3584x over previous
#include <cuda_runtime.h>
#include <cuda_fp16.h>
#include <cstdint>
#include <cstddef>

// Problem dims (fixed by the dataset)
#define SEQ_L 2048
#define BATCH 8
#define DIM   2048
#define M_ROWS (SEQ_L * BATCH)   // 16384
#define K_DIM  DIM
#define N_DIM  DIM
#define LANES  (BATCH * DIM)     // 16384

// Scan segmentation
#define NSEG 8
#define SEGLEN (SEQ_L / NSEG)    // 256

// GEMM tiling: CTA 128(M) x 128(N), 4 warps of 64x64, KT=32 (64B rows)
// 128-thread CTAs -> 2 CTAs/SM co-resident: cross-CTA overlap hides sync/LDSM bubbles.
#define MT 128
#define NT 128
#define KT 32
#define NCHUNK (K_DIM / KT)      // 64
#define ROWB 80                  // 64B data + 16B pad (conflict-free ldmatrix)

#define OFF_A 0
#define OFF_B (128 * ROWB)           // 10240
#define STAGE ((128 + 128) * ROWB)   // 20480
#define SMEM_TOTAL (2 * STAGE)       // 40960 per CTA -> 2 CTAs/SM

// Scratch (device globals — allocation-free rule)
__device__ __half g_ah[(size_t)M_ROWS * K_DIM];
__device__ __half g_wh[(size_t)N_DIM * K_DIM];
__device__ float  g_segend[NSEG * LANES];

// ---------------- PTX helpers (sm_80-era only: safe at compute_103) ----------------
__device__ __forceinline__ uint32_t smem_u32(const void* p) {
    uint32_t a;
    asm("{ .reg .u64 t; cvta.to.shared.u64 t, %1; cvt.u32.u64 %0, t; }"
        : "=r"(a) : "l"(p));
    return a;
}

__device__ __forceinline__ void cp_async16(uint32_t saddr, const void* gaddr) {
    asm volatile("cp.async.cg.shared.global [%0], [%1], 16;"
                 :: "r"(saddr), "l"(gaddr) : "memory");
}

__device__ __forceinline__ void ldsm_x4(uint32_t (&r)[4], uint32_t addr) {
    asm volatile("ldmatrix.sync.aligned.m8n8.x4.shared.b16 {%0,%1,%2,%3}, [%4];"
                 : "=r"(r[0]), "=r"(r[1]), "=r"(r[2]), "=r"(r[3]) : "r"(addr));
}

__device__ __forceinline__ void mma_f16(float (&d)[4], const uint32_t (&a)[4],
                                        const uint32_t* b) {
    asm volatile(
        "mma.sync.aligned.m16n8k16.row.col.f32.f16.f16.f32 "
        "{%0,%1,%2,%3}, {%4,%5,%6,%7}, {%8,%9}, {%0,%1,%2,%3};"
        : "+f"(d[0]), "+f"(d[1]), "+f"(d[2]), "+f"(d[3])
        : "r"(a[0]), "r"(a[1]), "r"(a[2]), "r"(a[3]), "r"(b[0]), "r"(b[1]));
}

// ---------------- Scan phase A: per-segment local scan, save segment-end state ----
__global__ void __launch_bounds__(256) scanA_kernel(const float* __restrict__ x,
                                                    const float* __restrict__ fparam) {
    const int lane = blockIdx.x * blockDim.x + threadIdx.x;  // 0..16383
    const int seg = blockIdx.y;
    const float f = 1.0f / (1.0f + expf(-fparam[lane & (DIM - 1)]));
    const float* px = x + (size_t)seg * SEGLEN * LANES + lane;
    float c = 0.0f;
    constexpr int U = 16;
    for (int t = 0; t < SEGLEN; t += U) {
        float xv[U];
#pragma unroll
        for (int u = 0; u < U; u++) xv[u] = px[(t + u) * LANES];
#pragma unroll
        for (int u = 0; u < U; u++) c = fmaf(f, c, xv[u]);
    }
    g_segend[seg * LANES + lane] = c;
}

// ---------------- Scan phase B: propagate carry, rescan, emit fp16 ----------
__global__ void __launch_bounds__(256) scanB_kernel(const float* __restrict__ x,
                                                    const float* __restrict__ xml,
                                                    const float* __restrict__ fparam) {
    const int lane = blockIdx.x * blockDim.x + threadIdx.x;
    const int seg = blockIdx.y;
    const float f = 1.0f / (1.0f + expf(-fparam[lane & (DIM - 1)]));
    const float omf = 1.0f - f;

    // f^SEGLEN by repeated squaring (SEGLEN = 256 = 2^8)
    float f256 = f;
#pragma unroll
    for (int i = 0; i < 8; i++) f256 *= f256;

    // G = global conv state entering this segment; fs = f^(seg*SEGLEN)
    float G = 0.0f, fs = 1.0f;
    for (int s = 0; s < seg; s++) {
        G = fmaf(f256, G, g_segend[s * LANES + lane]);
        fs *= f256;
    }

    float c = G;
    float m = xml[lane] * fs;
    const float* px = x + (size_t)seg * SEGLEN * LANES + lane;
    __half* ph = g_ah + (size_t)seg * SEGLEN * LANES + lane;

    constexpr int U = 16;
    for (int t = 0; t < SEGLEN; t += U) {
        float xv[U];
#pragma unroll
        for (int u = 0; u < U; u++) xv[u] = px[(t + u) * LANES];
#pragma unroll
        for (int u = 0; u < U; u++) {
            c = fmaf(f, c, xv[u]);
            m *= f;
            ph[(t + u) * LANES] = __float2half_rn(fmaf(omf, c, m));
        }
    }
}

// ---------------- W -> fp16 ----------
__global__ void __launch_bounds__(256) whalf_kernel(const float* __restrict__ W) {
    const int i = blockIdx.x * blockDim.x + threadIdx.x;
    g_wh[i] = __float2half_rn(W[i]);
}

// ---------------- GEMM: 1-pass fp16, fp32 accum, 128-thread CTA ----------------
__device__ __forceinline__ void load_chunk(uint32_t sb, int tid, int m0, int n0, int ck) {
    const uint32_t tb = sb + (uint32_t)(ck & 1) * STAGE;
    const int koff = ck * KT;
    // A: 128 rows x 64B; 1 row per thread (4 x 16B)
    {
        const size_t ga = (size_t)(m0 + tid) * K_DIM + koff;
        const uint32_t sa = tb + OFF_A + (uint32_t)tid * ROWB;
#pragma unroll
        for (int s = 0; s < 4; s++) cp_async16(sa + s * 16, g_ah + ga + s * 8);
    }
    // B: 128 rows x 64B; 1 row per thread
    {
        const size_t gb = (size_t)(n0 + tid) * K_DIM + koff;
        const uint32_t sB = tb + OFF_B + (uint32_t)tid * ROWB;
#pragma unroll
        for (int s = 0; s < 4; s++) cp_async16(sB + s * 16, g_wh + gb + s * 8);
    }
    asm volatile("cp.async.commit_group;" ::: "memory");
}

__global__ void __launch_bounds__(128, 2) gemm_kernel(float* __restrict__ out) {
    extern __shared__ char smem[];
    const uint32_t sb = smem_u32(smem);
    const int tid = threadIdx.x;
    const int lid = tid & 31;
    const int wid = tid >> 5;
    const int wm = wid & 1;      // 2 warps along M (64 rows each)
    const int wn = wid >> 1;     // 2 warps along N (64 cols each)
    const int n0 = blockIdx.x * NT;
    const int m0 = blockIdx.y * MT;

    float acc[4][8][4];
#pragma unroll
    for (int a = 0; a < 4; a++)
#pragma unroll
        for (int b = 0; b < 8; b++)
#pragma unroll
            for (int c = 0; c < 4; c++) acc[a][b][c] = 0.0f;

    // ldmatrix per-lane relative offsets (layouts validated in R4-R8 passes).
    uint32_t relA[4], relB[4];
#pragma unroll
    for (int mt = 0; mt < 4; mt++)
        relA[mt] = (uint32_t)((wm * 64 + mt * 16 + (lid & 15)) * ROWB + (lid >> 4) * 16);
#pragma unroll
    for (int p = 0; p < 4; p++)
        relB[p] = (uint32_t)((wn * 64 + p * 16 + ((lid >> 4) << 3) + (lid & 7)) * ROWB
                             + ((lid >> 3) & 1) * 16);

    load_chunk(sb, tid, m0, n0, 0);

    for (int i = 0; i < NCHUNK; i++) {
        if (i + 1 < NCHUNK) {
            load_chunk(sb, tid, m0, n0, i + 1);
            asm volatile("cp.async.wait_group 1;" ::: "memory");
        } else {
            asm volatile("cp.async.wait_group 0;" ::: "memory");
        }
        __syncthreads();

        const uint32_t base = sb + (uint32_t)(i & 1) * STAGE;
#pragma unroll
        for (int ks = 0; ks < 2; ks++) {
            const uint32_t ko = (uint32_t)ks * 32;
            uint32_t afr[4][4], bfr[4][4];
#pragma unroll
            for (int mt = 0; mt < 4; mt++) ldsm_x4(afr[mt], base + OFF_A + relA[mt] + ko);
#pragma unroll
            for (int p = 0; p < 4; p++)   ldsm_x4(bfr[p], base + OFF_B + relB[p] + ko);
#pragma unroll
            for (int mt = 0; mt < 4; mt++)
#pragma unroll
                for (int nt = 0; nt < 8; nt++)
                    mma_f16(acc[mt][nt], afr[mt], &bfr[nt >> 1][(nt & 1) * 2]);
        }
        __syncthreads();
    }

    // Epilogue: fragment lane l -> row l/4 (+8), cols 2(l%4), +1.
    const int l4 = lid >> 2;
    const int l2 = (lid & 3) * 2;
#pragma unroll
    for (int mt = 0; mt < 4; mt++) {
        const int r0 = m0 + wm * 64 + mt * 16 + l4;
#pragma unroll
        for (int nt = 0; nt < 8; nt++) {
            const int cn = n0 + wn * 64 + nt * 8 + l2;
            *reinterpret_cast<float2*>(out + (size_t)r0 * N_DIM + cn) =
                make_float2(acc[mt][nt][0], acc[mt][nt][1]);
            *reinterpret_cast<float2*>(out + (size_t)(r0 + 8) * N_DIM + cn) =
                make_float2(acc[mt][nt][2], acc[mt][nt][3]);
        }
    }
}

// ---------------- launch ----------------
extern "C" void kernel_launch(void* const* d_in, const int* in_sizes, int n_in,
                              void* d_out, int out_size) {
    const float *x = nullptr, *xml = nullptr, *fp = nullptr, *W = nullptr;
    for (int i = 0; i < n_in; i++) {
        int s = in_sizes[i];
        if (s == SEQ_L * BATCH * DIM)      x   = (const float*)d_in[i];
        else if (s == BATCH * DIM)         xml = (const float*)d_in[i];
        else if (s == DIM)                 fp  = (const float*)d_in[i];
        else if (s == DIM * DIM)           W   = (const float*)d_in[i];
    }

    cudaFuncSetAttribute(gemm_kernel, cudaFuncAttributeMaxDynamicSharedMemorySize, SMEM_TOTAL);

    scanA_kernel<<<dim3(LANES / 256, NSEG), 256>>>(x, fp);
    scanB_kernel<<<dim3(LANES / 256, NSEG), 256>>>(x, xml, fp);
    whalf_kernel<<<(N_DIM * K_DIM) / 256, 256>>>(W);
    gemm_kernel<<<dim3(N_DIM / NT, M_ROWS / MT), 128, SMEM_TOTAL>>>((float*)d_out);
}

// round 10
// speedup vs baseline: 1.3870x; 1.0211x over previous
#include <cuda_runtime.h>
#include <cuda_fp16.h>
#include <cstdint>
#include <cstddef>

// Problem dims (fixed by the dataset)
#define SEQ_L 2048
#define BATCH 8
#define DIM   2048
#define M_ROWS (SEQ_L * BATCH)   // 16384
#define K_DIM  DIM
#define N_DIM  DIM
#define LANES  (BATCH * DIM)     // 16384

// Scan segmentation
#define NSEG 8
#define SEGLEN (SEQ_L / NSEG)    // 256

// GEMM tiling: CTA 128(M) x 128(N), 256 threads, 8 warps of 64x32, KT=32.
// 64-reg accumulators -> ~116 regs -> 2 CTAs/SM = 16 warps/SM (R6's proven
// occupancy shape, which ran at 95-98% of the HMMA issue floor).
#define MT 128
#define NT 128
#define KT 32
#define NCHUNK (K_DIM / KT)      // 64
#define ROWB 80                  // 64B data + 16B pad (conflict-free ldmatrix)

#define OFF_A 0
#define OFF_B (128 * ROWB)           // 10240
#define STAGE ((128 + 128) * ROWB)   // 20480
#define SMEM_TOTAL (2 * STAGE)       // 40960 per CTA -> 2 CTAs/SM

// Scratch (device globals — allocation-free rule)
__device__ __half g_ah[(size_t)M_ROWS * K_DIM];
__device__ __half g_wh[(size_t)N_DIM * K_DIM];
__device__ float  g_segend[NSEG * LANES];

// ---------------- PTX helpers (sm_80-era only: safe at compute_103) ----------------
__device__ __forceinline__ uint32_t smem_u32(const void* p) {
    uint32_t a;
    asm("{ .reg .u64 t; cvta.to.shared.u64 t, %1; cvt.u32.u64 %0, t; }"
        : "=r"(a) : "l"(p));
    return a;
}

__device__ __forceinline__ void cp_async16(uint32_t saddr, const void* gaddr) {
    asm volatile("cp.async.cg.shared.global [%0], [%1], 16;"
                 :: "r"(saddr), "l"(gaddr) : "memory");
}

__device__ __forceinline__ void ldsm_x4(uint32_t (&r)[4], uint32_t addr) {
    asm volatile("ldmatrix.sync.aligned.m8n8.x4.shared.b16 {%0,%1,%2,%3}, [%4];"
                 : "=r"(r[0]), "=r"(r[1]), "=r"(r[2]), "=r"(r[3]) : "r"(addr));
}

__device__ __forceinline__ void mma_f16(float (&d)[4], const uint32_t (&a)[4],
                                        const uint32_t* b) {
    asm volatile(
        "mma.sync.aligned.m16n8k16.row.col.f32.f16.f16.f32 "
        "{%0,%1,%2,%3}, {%4,%5,%6,%7}, {%8,%9}, {%0,%1,%2,%3};"
        : "+f"(d[0]), "+f"(d[1]), "+f"(d[2]), "+f"(d[3])
        : "r"(a[0]), "r"(a[1]), "r"(a[2]), "r"(a[3]), "r"(b[0]), "r"(b[1]));
}

// ---------------- Scan phase A: per-segment local scan, save segment-end state ----
__global__ void __launch_bounds__(256) scanA_kernel(const float* __restrict__ x,
                                                    const float* __restrict__ fparam) {
    const int lane = blockIdx.x * blockDim.x + threadIdx.x;  // 0..16383
    const int seg = blockIdx.y;
    const float f = 1.0f / (1.0f + expf(-fparam[lane & (DIM - 1)]));
    const float* px = x + (size_t)seg * SEGLEN * LANES + lane;
    float c = 0.0f;
    constexpr int U = 16;
    for (int t = 0; t < SEGLEN; t += U) {
        float xv[U];
#pragma unroll
        for (int u = 0; u < U; u++) xv[u] = px[(t + u) * LANES];
#pragma unroll
        for (int u = 0; u < U; u++) c = fmaf(f, c, xv[u]);
    }
    g_segend[seg * LANES + lane] = c;
}

// ---------------- Scan phase B: propagate carry, rescan, emit fp16 ----------
__global__ void __launch_bounds__(256) scanB_kernel(const float* __restrict__ x,
                                                    const float* __restrict__ xml,
                                                    const float* __restrict__ fparam) {
    const int lane = blockIdx.x * blockDim.x + threadIdx.x;
    const int seg = blockIdx.y;
    const float f = 1.0f / (1.0f + expf(-fparam[lane & (DIM - 1)]));
    const float omf = 1.0f - f;

    // f^SEGLEN by repeated squaring (SEGLEN = 256 = 2^8)
    float f256 = f;
#pragma unroll
    for (int i = 0; i < 8; i++) f256 *= f256;

    // G = global conv state entering this segment; fs = f^(seg*SEGLEN)
    float G = 0.0f, fs = 1.0f;
    for (int s = 0; s < seg; s++) {
        G = fmaf(f256, G, g_segend[s * LANES + lane]);
        fs *= f256;
    }

    float c = G;
    float m = xml[lane] * fs;
    const float* px = x + (size_t)seg * SEGLEN * LANES + lane;
    __half* ph = g_ah + (size_t)seg * SEGLEN * LANES + lane;

    constexpr int U = 16;
    for (int t = 0; t < SEGLEN; t += U) {
        float xv[U];
#pragma unroll
        for (int u = 0; u < U; u++) xv[u] = px[(t + u) * LANES];
#pragma unroll
        for (int u = 0; u < U; u++) {
            c = fmaf(f, c, xv[u]);
            m *= f;
            ph[(t + u) * LANES] = __float2half_rn(fmaf(omf, c, m));
        }
    }
}

// ---------------- W -> fp16 ----------
__global__ void __launch_bounds__(256) whalf_kernel(const float* __restrict__ W) {
    const int i = blockIdx.x * blockDim.x + threadIdx.x;
    g_wh[i] = __float2half_rn(W[i]);
}

// ---------------- GEMM: 1-pass fp16, fp32 accum, 256 threads, 64x32 warp tile ----
__device__ __forceinline__ void load_chunk(uint32_t sb, int tid, int m0, int n0, int ck) {
    const uint32_t tb = sb + (uint32_t)(ck & 1) * STAGE;
    const int koff = ck * KT;
    const int row = tid & 127;
    if (tid < 128) {
        // A: 128 rows x 64B; 1 row per thread (4 x 16B)
        const size_t ga = (size_t)(m0 + row) * K_DIM + koff;
        const uint32_t sa = tb + OFF_A + (uint32_t)row * ROWB;
#pragma unroll
        for (int s = 0; s < 4; s++) cp_async16(sa + s * 16, g_ah + ga + s * 8);
    } else {
        // B: 128 rows x 64B; 1 row per thread
        const size_t gb = (size_t)(n0 + row) * K_DIM + koff;
        const uint32_t sB = tb + OFF_B + (uint32_t)row * ROWB;
#pragma unroll
        for (int s = 0; s < 4; s++) cp_async16(sB + s * 16, g_wh + gb + s * 8);
    }
    asm volatile("cp.async.commit_group;" ::: "memory");
}

__global__ void __launch_bounds__(256, 2) gemm_kernel(float* __restrict__ out) {
    extern __shared__ char smem[];
    const uint32_t sb = smem_u32(smem);
    const int tid = threadIdx.x;
    const int lid = tid & 31;
    const int wid = tid >> 5;
    const int wm = wid & 1;      // 2 warps along M (64 rows each)
    const int wn = wid >> 1;     // 4 warps along N (32 cols each)
    const int n0 = blockIdx.x * NT;
    const int m0 = blockIdx.y * MT;

    float acc[4][4][4];
#pragma unroll
    for (int a = 0; a < 4; a++)
#pragma unroll
        for (int b = 0; b < 4; b++)
#pragma unroll
            for (int c = 0; c < 4; c++) acc[a][b][c] = 0.0f;

    // ldmatrix per-lane relative offsets (layouts validated in R4-R9 passes).
    uint32_t relA[4], relB[2];
#pragma unroll
    for (int mt = 0; mt < 4; mt++)
        relA[mt] = (uint32_t)((wm * 64 + mt * 16 + (lid & 15)) * ROWB + (lid >> 4) * 16);
#pragma unroll
    for (int p = 0; p < 2; p++)
        relB[p] = (uint32_t)((wn * 32 + p * 16 + ((lid >> 4) << 3) + (lid & 7)) * ROWB
                             + ((lid >> 3) & 1) * 16);

    load_chunk(sb, tid, m0, n0, 0);

    for (int i = 0; i < NCHUNK; i++) {
        if (i + 1 < NCHUNK) {
            load_chunk(sb, tid, m0, n0, i + 1);
            asm volatile("cp.async.wait_group 1;" ::: "memory");
        } else {
            asm volatile("cp.async.wait_group 0;" ::: "memory");
        }
        __syncthreads();

        const uint32_t base = sb + (uint32_t)(i & 1) * STAGE;
#pragma unroll
        for (int ks = 0; ks < 2; ks++) {
            const uint32_t ko = (uint32_t)ks * 32;
            uint32_t afr[4][4], bfr[2][4];
#pragma unroll
            for (int mt = 0; mt < 4; mt++) ldsm_x4(afr[mt], base + OFF_A + relA[mt] + ko);
#pragma unroll
            for (int p = 0; p < 2; p++)   ldsm_x4(bfr[p], base + OFF_B + relB[p] + ko);
#pragma unroll
            for (int mt = 0; mt < 4; mt++)
#pragma unroll
                for (int nt = 0; nt < 4; nt++)
                    mma_f16(acc[mt][nt], afr[mt], &bfr[nt >> 1][(nt & 1) * 2]);
        }
        __syncthreads();
    }

    // Epilogue: fragment lane l -> row l/4 (+8), cols 2(l%4), +1.
    const int l4 = lid >> 2;
    const int l2 = (lid & 3) * 2;
#pragma unroll
    for (int mt = 0; mt < 4; mt++) {
        const int r0 = m0 + wm * 64 + mt * 16 + l4;
#pragma unroll
        for (int nt = 0; nt < 4; nt++) {
            const int cn = n0 + wn * 32 + nt * 8 + l2;
            *reinterpret_cast<float2*>(out + (size_t)r0 * N_DIM + cn) =
                make_float2(acc[mt][nt][0], acc[mt][nt][1]);
            *reinterpret_cast<float2*>(out + (size_t)(r0 + 8) * N_DIM + cn) =
                make_float2(acc[mt][nt][2], acc[mt][nt][3]);
        }
    }
}

// ---------------- launch ----------------
extern "C" void kernel_launch(void* const* d_in, const int* in_sizes, int n_in,
                              void* d_out, int out_size) {
    const float *x = nullptr, *xml = nullptr, *fp = nullptr, *W = nullptr;
    for (int i = 0; i < n_in; i++) {
        int s = in_sizes[i];
        if (s == SEQ_L * BATCH * DIM)      x   = (const float*)d_in[i];
        else if (s == BATCH * DIM)         xml = (const float*)d_in[i];
        else if (s == DIM)                 fp  = (const float*)d_in[i];
        else if (s == DIM * DIM)           W   = (const float*)d_in[i];
    }

    cudaFuncSetAttribute(gemm_kernel, cudaFuncAttributeMaxDynamicSharedMemorySize, SMEM_TOTAL);

    scanA_kernel<<<dim3(LANES / 256, NSEG), 256>>>(x, fp);
    scanB_kernel<<<dim3(LANES / 256, NSEG), 256>>>(x, xml, fp);
    whalf_kernel<<<(N_DIM * K_DIM) / 256, 256>>>(W);
    gemm_kernel<<<dim3(N_DIM / NT, M_ROWS / MT), 256, SMEM_TOTAL>>>((float*)d_out);
}

// round 11
// speedup vs baseline: 1.4764x; 1.0645x over previous
#include <cuda_runtime.h>
#include <cuda_fp16.h>
#include <cstdint>
#include <cstddef>

// Problem dims (fixed by the dataset)
#define SEQ_L 2048
#define BATCH 8
#define DIM   2048
#define M_ROWS (SEQ_L * BATCH)   // 16384
#define K_DIM  DIM
#define N_DIM  DIM
#define LANES  (BATCH * DIM)     // 16384

// Scan segmentation
#define NSEG 8
#define SEGLEN (SEQ_L / NSEG)    // 256

// GEMM tiling: CTA 128(M) x 128(N), 256 threads, 8 warps of 64x32, KT=32.
// 3-stage cp.async ring, ONE __syncthreads per chunk.
#define MT 128
#define NT 128
#define KT 32
#define NCHUNK (K_DIM / KT)      // 64
#define ROWB 80                  // 64B data + 16B pad (conflict-free ldmatrix)
#define NSTAGE 3

#define OFF_A 0
#define OFF_B (128 * ROWB)           // 10240
#define STAGE ((128 + 128) * ROWB)   // 20480
#define SMEM_TOTAL (NSTAGE * STAGE)  // 61440 per CTA -> 2 CTAs/SM

// Scratch (device globals — allocation-free rule)
__device__ __half g_ah[(size_t)M_ROWS * K_DIM];
__device__ __half g_wh[(size_t)N_DIM * K_DIM];
__device__ float  g_segend[NSEG * LANES];

// ---------------- PTX helpers (sm_80-era only: safe at compute_103) ----------------
__device__ __forceinline__ uint32_t smem_u32(const void* p) {
    uint32_t a;
    asm("{ .reg .u64 t; cvta.to.shared.u64 t, %1; cvt.u32.u64 %0, t; }"
        : "=r"(a) : "l"(p));
    return a;
}

__device__ __forceinline__ void cp_async16(uint32_t saddr, const void* gaddr) {
    asm volatile("cp.async.cg.shared.global [%0], [%1], 16;"
                 :: "r"(saddr), "l"(gaddr) : "memory");
}

__device__ __forceinline__ void ldsm_x4(uint32_t (&r)[4], uint32_t addr) {
    asm volatile("ldmatrix.sync.aligned.m8n8.x4.shared.b16 {%0,%1,%2,%3}, [%4];"
                 : "=r"(r[0]), "=r"(r[1]), "=r"(r[2]), "=r"(r[3]) : "r"(addr));
}

__device__ __forceinline__ void mma_f16(float (&d)[4], const uint32_t (&a)[4],
                                        const uint32_t* b) {
    asm volatile(
        "mma.sync.aligned.m16n8k16.row.col.f32.f16.f16.f32 "
        "{%0,%1,%2,%3}, {%4,%5,%6,%7}, {%8,%9}, {%0,%1,%2,%3};"
        : "+f"(d[0]), "+f"(d[1]), "+f"(d[2]), "+f"(d[3])
        : "r"(a[0]), "r"(a[1]), "r"(a[2]), "r"(a[3]), "r"(b[0]), "r"(b[1]));
}

// ---------------- Scan phase A: per-segment local scan, save segment-end state ----
__global__ void __launch_bounds__(256) scanA_kernel(const float* __restrict__ x,
                                                    const float* __restrict__ fparam) {
    const int lane = blockIdx.x * blockDim.x + threadIdx.x;  // 0..16383
    const int seg = blockIdx.y;
    const float f = 1.0f / (1.0f + expf(-fparam[lane & (DIM - 1)]));
    const float* px = x + (size_t)seg * SEGLEN * LANES + lane;
    float c = 0.0f;
    constexpr int U = 16;
    for (int t = 0; t < SEGLEN; t += U) {
        float xv[U];
#pragma unroll
        for (int u = 0; u < U; u++) xv[u] = px[(t + u) * LANES];
#pragma unroll
        for (int u = 0; u < U; u++) c = fmaf(f, c, xv[u]);
    }
    g_segend[seg * LANES + lane] = c;
}

// ---------------- Scan phase B: propagate carry, rescan, emit fp16 ----------
__global__ void __launch_bounds__(256) scanB_kernel(const float* __restrict__ x,
                                                    const float* __restrict__ xml,
                                                    const float* __restrict__ fparam) {
    const int lane = blockIdx.x * blockDim.x + threadIdx.x;
    const int seg = blockIdx.y;
    const float f = 1.0f / (1.0f + expf(-fparam[lane & (DIM - 1)]));
    const float omf = 1.0f - f;

    // f^SEGLEN by repeated squaring (SEGLEN = 256 = 2^8)
    float f256 = f;
#pragma unroll
    for (int i = 0; i < 8; i++) f256 *= f256;

    // G = global conv state entering this segment; fs = f^(seg*SEGLEN)
    float G = 0.0f, fs = 1.0f;
    for (int s = 0; s < seg; s++) {
        G = fmaf(f256, G, g_segend[s * LANES + lane]);
        fs *= f256;
    }

    float c = G;
    float m = xml[lane] * fs;
    const float* px = x + (size_t)seg * SEGLEN * LANES + lane;
    __half* ph = g_ah + (size_t)seg * SEGLEN * LANES + lane;

    constexpr int U = 16;
    for (int t = 0; t < SEGLEN; t += U) {
        float xv[U];
#pragma unroll
        for (int u = 0; u < U; u++) xv[u] = px[(t + u) * LANES];
#pragma unroll
        for (int u = 0; u < U; u++) {
            c = fmaf(f, c, xv[u]);
            m *= f;
            ph[(t + u) * LANES] = __float2half_rn(fmaf(omf, c, m));
        }
    }
}

// ---------------- W -> fp16 ----------
__global__ void __launch_bounds__(256) whalf_kernel(const float* __restrict__ W) {
    const int i = blockIdx.x * blockDim.x + threadIdx.x;
    g_wh[i] = __float2half_rn(W[i]);
}

// ---------------- GEMM: 1-pass fp16, fp32 accum, 3-stage single-sync pipeline ----
__device__ __forceinline__ void load_chunk(uint32_t sb, int tid, int m0, int n0,
                                           int ck, int stage) {
    const uint32_t tb = sb + (uint32_t)stage * STAGE;
    const int koff = ck * KT;
    const int row = tid & 127;
    if (tid < 128) {
        // A: 128 rows x 64B; 1 row per thread (4 x 16B)
        const size_t ga = (size_t)(m0 + row) * K_DIM + koff;
        const uint32_t sa = tb + OFF_A + (uint32_t)row * ROWB;
#pragma unroll
        for (int s = 0; s < 4; s++) cp_async16(sa + s * 16, g_ah + ga + s * 8);
    } else {
        // B: 128 rows x 64B; 1 row per thread
        const size_t gb = (size_t)(n0 + row) * K_DIM + koff;
        const uint32_t sB = tb + OFF_B + (uint32_t)row * ROWB;
#pragma unroll
        for (int s = 0; s < 4; s++) cp_async16(sB + s * 16, g_wh + gb + s * 8);
    }
    asm volatile("cp.async.commit_group;" ::: "memory");
}

__global__ void __launch_bounds__(256, 2) gemm_kernel(float* __restrict__ out) {
    extern __shared__ char smem[];
    const uint32_t sb = smem_u32(smem);
    const int tid = threadIdx.x;
    const int lid = tid & 31;
    const int wid = tid >> 5;
    const int wm = wid & 1;      // 2 warps along M (64 rows each)
    const int wn = wid >> 1;     // 4 warps along N (32 cols each)
    const int n0 = blockIdx.x * NT;
    const int m0 = blockIdx.y * MT;

    float acc[4][4][4];
#pragma unroll
    for (int a = 0; a < 4; a++)
#pragma unroll
        for (int b = 0; b < 4; b++)
#pragma unroll
            for (int c = 0; c < 4; c++) acc[a][b][c] = 0.0f;

    // ldmatrix per-lane relative offsets (layouts validated in R4-R10 passes).
    uint32_t relA[4], relB[2];
#pragma unroll
    for (int mt = 0; mt < 4; mt++)
        relA[mt] = (uint32_t)((wm * 64 + mt * 16 + (lid & 15)) * ROWB + (lid >> 4) * 16);
#pragma unroll
    for (int p = 0; p < 2; p++)
        relB[p] = (uint32_t)((wn * 32 + p * 16 + ((lid >> 4) << 3) + (lid & 7)) * ROWB
                             + ((lid >> 3) & 1) * 16);

    // Prologue: stages 0 and 1 in flight.
    load_chunk(sb, tid, m0, n0, 0, 0);
    load_chunk(sb, tid, m0, n0, 1, 1);

    int stage = 0;       // stage holding chunk i
    int wstage = 2;      // stage to write chunk i+2 into

    for (int i = 0; i < NCHUNK; i++) {
        // Chunk i ready when at most 1 newer group is still outstanding.
        if (i + 1 < NCHUNK) {
            asm volatile("cp.async.wait_group 1;" ::: "memory");
        } else {
            asm volatile("cp.async.wait_group 0;" ::: "memory");
        }
        // Single barrier: publishes chunk i to all warps AND retires all reads
        // of buffer `wstage` (last read at iter i-1), making it safe to refill.
        __syncthreads();

        if (i + 2 < NCHUNK) {
            load_chunk(sb, tid, m0, n0, i + 2, wstage);
        }

        const uint32_t base = sb + (uint32_t)stage * STAGE;
#pragma unroll
        for (int ks = 0; ks < 2; ks++) {
            const uint32_t ko = (uint32_t)ks * 32;
            uint32_t afr[4][4], bfr[2][4];
#pragma unroll
            for (int mt = 0; mt < 4; mt++) ldsm_x4(afr[mt], base + OFF_A + relA[mt] + ko);
#pragma unroll
            for (int p = 0; p < 2; p++)   ldsm_x4(bfr[p], base + OFF_B + relB[p] + ko);
#pragma unroll
            for (int mt = 0; mt < 4; mt++)
#pragma unroll
                for (int nt = 0; nt < 4; nt++)
                    mma_f16(acc[mt][nt], afr[mt], &bfr[nt >> 1][(nt & 1) * 2]);
        }

        stage = (stage + 1 == NSTAGE) ? 0 : stage + 1;
        wstage = (wstage + 1 == NSTAGE) ? 0 : wstage + 1;
    }

    // Epilogue: fragment lane l -> row l/4 (+8), cols 2(l%4), +1.
    const int l4 = lid >> 2;
    const int l2 = (lid & 3) * 2;
#pragma unroll
    for (int mt = 0; mt < 4; mt++) {
        const int r0 = m0 + wm * 64 + mt * 16 + l4;
#pragma unroll
        for (int nt = 0; nt < 4; nt++) {
            const int cn = n0 + wn * 32 + nt * 8 + l2;
            *reinterpret_cast<float2*>(out + (size_t)r0 * N_DIM + cn) =
                make_float2(acc[mt][nt][0], acc[mt][nt][1]);
            *reinterpret_cast<float2*>(out + (size_t)(r0 + 8) * N_DIM + cn) =
                make_float2(acc[mt][nt][2], acc[mt][nt][3]);
        }
    }
}

// ---------------- launch ----------------
extern "C" void kernel_launch(void* const* d_in, const int* in_sizes, int n_in,
                              void* d_out, int out_size) {
    const float *x = nullptr, *xml = nullptr, *fp = nullptr, *W = nullptr;
    for (int i = 0; i < n_in; i++) {
        int s = in_sizes[i];
        if (s == SEQ_L * BATCH * DIM)      x   = (const float*)d_in[i];
        else if (s == BATCH * DIM)         xml = (const float*)d_in[i];
        else if (s == DIM)                 fp  = (const float*)d_in[i];
        else if (s == DIM * DIM)           W   = (const float*)d_in[i];
    }

    cudaFuncSetAttribute(gemm_kernel, cudaFuncAttributeMaxDynamicSharedMemorySize, SMEM_TOTAL);

    scanA_kernel<<<dim3(LANES / 256, NSEG), 256>>>(x, fp);
    scanB_kernel<<<dim3(LANES / 256, NSEG), 256>>>(x, xml, fp);
    whalf_kernel<<<(N_DIM * K_DIM) / 256, 256>>>(W);
    gemm_kernel<<<dim3(N_DIM / NT, M_ROWS / MT), 256, SMEM_TOTAL>>>((float*)d_out);
}

// round 12
// speedup vs baseline: 2.0729x; 1.4040x over previous
#include <cuda_runtime.h>
#include <cuda_fp16.h>
#include <cstdint>
#include <cstddef>

// Problem dims (fixed by the dataset)
#define SEQ_L 2048
#define BATCH 8
#define DIM   2048
#define M_ROWS (SEQ_L * BATCH)   // 16384
#define K_DIM  DIM
#define N_DIM  DIM
#define LANES  (BATCH * DIM)     // 16384

// Scan segmentation
#define NSEG 8
#define SEGLEN (SEQ_L / NSEG)    // 256

// GEMM tiling: CTA 128(M) x 128(N), 256 threads, 8 warps of 64x32, KT=64.
// Un-padded 128B rows with XOR swizzle (chunk c^(row&7)); 3-stage ring,
// ONE __syncthreads per chunk (32 chunks).
#define MT 128
#define NT 128
#define KT 64
#define NCHUNK (K_DIM / KT)      // 32
#define ROWB 128                 // 128B rows, swizzled (no pad)
#define NSTAGE 3

#define OFF_A 0
#define OFF_B (128 * ROWB)           // 16384
#define STAGE ((128 + 128) * ROWB)   // 32768
#define SMEM_TOTAL (NSTAGE * STAGE)  // 98304 per CTA -> 2 CTAs/SM (196KB < 227KB)

// Scratch (device globals — allocation-free rule)
__device__ __half g_ah[(size_t)M_ROWS * K_DIM];
__device__ __half g_wh[(size_t)N_DIM * K_DIM];
__device__ float  g_segend[NSEG * LANES];

// ---------------- PTX helpers (sm_80-era only: safe at compute_103) ----------------
__device__ __forceinline__ uint32_t smem_u32(const void* p) {
    uint32_t a;
    asm("{ .reg .u64 t; cvta.to.shared.u64 t, %1; cvt.u32.u64 %0, t; }"
        : "=r"(a) : "l"(p));
    return a;
}

__device__ __forceinline__ void cp_async16(uint32_t saddr, const void* gaddr) {
    asm volatile("cp.async.cg.shared.global [%0], [%1], 16;"
                 :: "r"(saddr), "l"(gaddr) : "memory");
}

__device__ __forceinline__ void ldsm_x4(uint32_t (&r)[4], uint32_t addr) {
    asm volatile("ldmatrix.sync.aligned.m8n8.x4.shared.b16 {%0,%1,%2,%3}, [%4];"
                 : "=r"(r[0]), "=r"(r[1]), "=r"(r[2]), "=r"(r[3]) : "r"(addr));
}

__device__ __forceinline__ void mma_f16(float (&d)[4], const uint32_t (&a)[4],
                                        const uint32_t* b) {
    asm volatile(
        "mma.sync.aligned.m16n8k16.row.col.f32.f16.f16.f32 "
        "{%0,%1,%2,%3}, {%4,%5,%6,%7}, {%8,%9}, {%0,%1,%2,%3};"
        : "+f"(d[0]), "+f"(d[1]), "+f"(d[2]), "+f"(d[3])
        : "r"(a[0]), "r"(a[1]), "r"(a[2]), "r"(a[3]), "r"(b[0]), "r"(b[1]));
}

// ---------------- Scan phase A: per-segment local scan, save segment-end state ----
__global__ void __launch_bounds__(256) scanA_kernel(const float* __restrict__ x,
                                                    const float* __restrict__ fparam) {
    const int lane = blockIdx.x * blockDim.x + threadIdx.x;  // 0..16383
    const int seg = blockIdx.y;
    const float f = 1.0f / (1.0f + expf(-fparam[lane & (DIM - 1)]));
    const float* px = x + (size_t)seg * SEGLEN * LANES + lane;
    float c = 0.0f;
    constexpr int U = 16;
    for (int t = 0; t < SEGLEN; t += U) {
        float xv[U];
#pragma unroll
        for (int u = 0; u < U; u++) xv[u] = px[(t + u) * LANES];
#pragma unroll
        for (int u = 0; u < U; u++) c = fmaf(f, c, xv[u]);
    }
    g_segend[seg * LANES + lane] = c;
}

// ---------------- Scan phase B: propagate carry, rescan, emit fp16 ----------
__global__ void __launch_bounds__(256) scanB_kernel(const float* __restrict__ x,
                                                    const float* __restrict__ xml,
                                                    const float* __restrict__ fparam) {
    const int lane = blockIdx.x * blockDim.x + threadIdx.x;
    const int seg = blockIdx.y;
    const float f = 1.0f / (1.0f + expf(-fparam[lane & (DIM - 1)]));
    const float omf = 1.0f - f;

    // f^SEGLEN by repeated squaring (SEGLEN = 256 = 2^8)
    float f256 = f;
#pragma unroll
    for (int i = 0; i < 8; i++) f256 *= f256;

    // G = global conv state entering this segment; fs = f^(seg*SEGLEN)
    float G = 0.0f, fs = 1.0f;
    for (int s = 0; s < seg; s++) {
        G = fmaf(f256, G, g_segend[s * LANES + lane]);
        fs *= f256;
    }

    float c = G;
    float m = xml[lane] * fs;
    const float* px = x + (size_t)seg * SEGLEN * LANES + lane;
    __half* ph = g_ah + (size_t)seg * SEGLEN * LANES + lane;

    constexpr int U = 16;
    for (int t = 0; t < SEGLEN; t += U) {
        float xv[U];
#pragma unroll
        for (int u = 0; u < U; u++) xv[u] = px[(t + u) * LANES];
#pragma unroll
        for (int u = 0; u < U; u++) {
            c = fmaf(f, c, xv[u]);
            m *= f;
            ph[(t + u) * LANES] = __float2half_rn(fmaf(omf, c, m));
        }
    }
}

// ---------------- W -> fp16 ----------
__global__ void __launch_bounds__(256) whalf_kernel(const float* __restrict__ W) {
    const int i = blockIdx.x * blockDim.x + threadIdx.x;
    g_wh[i] = __float2half_rn(W[i]);
}

// ---------------- GEMM: 1-pass fp16, fp32 accum, KT=64 swizzled, single sync ----
// smem row r (128B) stores logical 16B-chunk c at physical chunk (c ^ (r&7)).
__device__ __forceinline__ void load_chunk(uint32_t sb, int tid, int m0, int n0,
                                           int ck, int stage) {
    const uint32_t tb = sb + (uint32_t)stage * STAGE;
    const int koff = ck * KT;
    const int row = tid >> 1;        // 0..127
    const int half = tid & 1;        // 64B half of the row
    const int sw = row & 7;
    // A: 128 rows x 128B
    {
        const size_t ga = (size_t)(m0 + row) * K_DIM + koff + half * 32;
        const uint32_t sa = tb + OFF_A + (uint32_t)row * ROWB;
#pragma unroll
        for (int s = 0; s < 4; s++) {
            const int c = half * 4 + s;
            cp_async16(sa + (uint32_t)((c ^ sw) << 4), g_ah + ga + s * 8);
        }
    }
    // B: 128 rows x 128B
    {
        const size_t gb = (size_t)(n0 + row) * K_DIM + koff + half * 32;
        const uint32_t sB = tb + OFF_B + (uint32_t)row * ROWB;
#pragma unroll
        for (int s = 0; s < 4; s++) {
            const int c = half * 4 + s;
            cp_async16(sB + (uint32_t)((c ^ sw) << 4), g_wh + gb + s * 8);
        }
    }
    asm volatile("cp.async.commit_group;" ::: "memory");
}

__global__ void __launch_bounds__(256, 2) gemm_kernel(float* __restrict__ out) {
    extern __shared__ char smem[];
    const uint32_t sb = smem_u32(smem);
    const int tid = threadIdx.x;
    const int lid = tid & 31;
    const int wid = tid >> 5;
    const int wm = wid & 1;      // 2 warps along M (64 rows each)
    const int wn = wid >> 1;     // 4 warps along N (32 cols each)
    const int n0 = blockIdx.x * NT;
    const int m0 = blockIdx.y * MT;

    float acc[4][4][4];
#pragma unroll
    for (int a = 0; a < 4; a++)
#pragma unroll
        for (int b = 0; b < 4; b++)
#pragma unroll
            for (int c = 0; c < 4; c++) acc[a][b][c] = 0.0f;

    // Per-lane ldmatrix row bases (swizzle XOR applied per k-step).
    // A x4: row = wm*64 + mt*16 + (lid&15); 16B col base = (lid>>4).
    // B x4: row = wn*32 + p*16 + ((lid>>4)<<3) + (lid&7); col base = (lid>>3)&1.
    uint32_t aRow[4], aSw[4], bRow[2], bSw[2];
    const uint32_t aC = (uint32_t)(lid >> 4);
    const uint32_t bC = (uint32_t)((lid >> 3) & 1);
#pragma unroll
    for (int mt = 0; mt < 4; mt++) {
        const uint32_t r = (uint32_t)(wm * 64 + mt * 16 + (lid & 15));
        aRow[mt] = r * ROWB;
        aSw[mt] = r & 7;
    }
#pragma unroll
    for (int p = 0; p < 2; p++) {
        const uint32_t r = (uint32_t)(wn * 32 + p * 16 + ((lid >> 4) << 3) + (lid & 7));
        bRow[p] = r * ROWB;
        bSw[p] = r & 7;
    }

    // Prologue: stages 0 and 1 in flight.
    load_chunk(sb, tid, m0, n0, 0, 0);
    load_chunk(sb, tid, m0, n0, 1, 1);

    int stage = 0;       // stage holding chunk i
    int wstage = 2;      // stage to write chunk i+2 into

    for (int i = 0; i < NCHUNK; i++) {
        if (i + 1 < NCHUNK) {
            asm volatile("cp.async.wait_group 1;" ::: "memory");
        } else {
            asm volatile("cp.async.wait_group 0;" ::: "memory");
        }
        // Single barrier: publishes chunk i AND retires reads of buffer wstage.
        __syncthreads();

        if (i + 2 < NCHUNK) {
            load_chunk(sb, tid, m0, n0, i + 2, wstage);
        }

        const uint32_t baseA = sb + (uint32_t)stage * STAGE + OFF_A;
        const uint32_t baseB = sb + (uint32_t)stage * STAGE + OFF_B;
#pragma unroll
        for (int ks = 0; ks < 4; ks++) {
            uint32_t afr[4][4], bfr[2][4];
#pragma unroll
            for (int mt = 0; mt < 4; mt++)
                ldsm_x4(afr[mt], baseA + aRow[mt]
                                 + (((aC + 2u * ks) ^ aSw[mt]) << 4));
#pragma unroll
            for (int p = 0; p < 2; p++)
                ldsm_x4(bfr[p], baseB + bRow[p]
                                + (((bC + 2u * ks) ^ bSw[p]) << 4));
#pragma unroll
            for (int mt = 0; mt < 4; mt++)
#pragma unroll
                for (int nt = 0; nt < 4; nt++)
                    mma_f16(acc[mt][nt], afr[mt], &bfr[nt >> 1][(nt & 1) * 2]);
        }

        stage = (stage + 1 == NSTAGE) ? 0 : stage + 1;
        wstage = (wstage + 1 == NSTAGE) ? 0 : wstage + 1;
    }

    // Epilogue: fragment lane l -> row l/4 (+8), cols 2(l%4), +1.
    const int l4 = lid >> 2;
    const int l2 = (lid & 3) * 2;
#pragma unroll
    for (int mt = 0; mt < 4; mt++) {
        const int r0 = m0 + wm * 64 + mt * 16 + l4;
#pragma unroll
        for (int nt = 0; nt < 4; nt++) {
            const int cn = n0 + wn * 32 + nt * 8 + l2;
            *reinterpret_cast<float2*>(out + (size_t)r0 * N_DIM + cn) =
                make_float2(acc[mt][nt][0], acc[mt][nt][1]);
            *reinterpret_cast<float2*>(out + (size_t)(r0 + 8) * N_DIM + cn) =
                make_float2(acc[mt][nt][2], acc[mt][nt][3]);
        }
    }
}

// ---------------- launch ----------------
extern "C" void kernel_launch(void* const* d_in, const int* in_sizes, int n_in,
                              void* d_out, int out_size) {
    const float *x = nullptr, *xml = nullptr, *fp = nullptr, *W = nullptr;
    for (int i = 0; i < n_in; i++) {
        int s = in_sizes[i];
        if (s == SEQ_L * BATCH * DIM)      x   = (const float*)d_in[i];
        else if (s == BATCH * DIM)         xml = (const float*)d_in[i];
        else if (s == DIM)                 fp  = (const float*)d_in[i];
        else if (s == DIM * DIM)           W   = (const float*)d_in[i];
    }

    cudaFuncSetAttribute(gemm_kernel, cudaFuncAttributeMaxDynamicSharedMemorySize, SMEM_TOTAL);

    scanA_kernel<<<dim3(LANES / 256, NSEG), 256>>>(x, fp);
    scanB_kernel<<<dim3(LANES / 256, NSEG), 256>>>(x, xml, fp);
    whalf_kernel<<<(N_DIM * K_DIM) / 256, 256>>>(W);
    gemm_kernel<<<dim3(N_DIM / NT, M_ROWS / MT), 256, SMEM_TOTAL>>>((float*)d_out);
}